// round 1
// baseline (speedup 1.0000x reference)
#include <cuda_runtime.h>

// Problem constants
#define S2    2048
#define HID   1024
#define NH    16
#define HD    64
#define BATCH 2
#define NROWS (BATCH * NH * S2)   // 65536 query rows total

// Scratch for projected Q and V in [B, H, S, d] layout (16 MB each).
__device__ float g_q[BATCH * NH * S2 * HD];
__device__ float g_v[BATCH * NH * S2 * HD];

// ---------------------------------------------------------------------------
// Projection GEMM: C[m, n] = A[m, :] @ W[:, n] + bias[n]
// A = hidden [4096 x 1024] row-major, W [1024 x 1024] row-major.
// Output written directly to [B,H,S,d] scratch (m = b*S+s, n = h*64+c).
// blockIdx.z: 0 -> (W_q, g_q), 1 -> (W_v, g_v)
// ---------------------------------------------------------------------------
#define BM 128
#define BN 128
#define BK 8
#define TM 8
#define TN 8

__global__ __launch_bounds__(256, 2)
void proj_kernel(const float* __restrict__ A,
                 const float* __restrict__ Wq, const float* __restrict__ bq,
                 const float* __restrict__ Wv, const float* __restrict__ bv)
{
    const float* __restrict__ W    = blockIdx.z ? Wv : Wq;
    const float* __restrict__ bias = blockIdx.z ? bv : bq;
    float* __restrict__ out        = blockIdx.z ? g_v : g_q;

    __shared__ float As[BK][BM];   // transposed A tile
    __shared__ float Bs[BK][BN];

    const int tid = threadIdx.x;
    const int m0  = blockIdx.y * BM;
    const int n0  = blockIdx.x * BN;

    // A tile loader: 128 rows x 8 k; one float4 per thread
    const int arow = tid >> 1;            // 0..127
    const int acol = (tid & 1) << 2;      // 0 or 4
    // B tile loader: 8 k-rows x 128 n; one float4 per thread
    const int brow = tid >> 5;            // 0..7
    const int bcol = (tid & 31) << 2;     // 0..124

    const int tRow = (tid >> 4) << 3;     // 0..120
    const int tCol = (tid & 15) << 3;     // 0..120

    const float* Ap = A + (m0 + arow) * HID + acol;
    const float* Wp = W + brow * HID + n0 + bcol;

    float acc[TM][TN];
    #pragma unroll
    for (int i = 0; i < TM; i++)
        #pragma unroll
        for (int j = 0; j < TN; j++) acc[i][j] = 0.0f;

    for (int k0 = 0; k0 < HID; k0 += BK) {
        float4 a4 = *(const float4*)(Ap + k0);
        As[acol + 0][arow] = a4.x;
        As[acol + 1][arow] = a4.y;
        As[acol + 2][arow] = a4.z;
        As[acol + 3][arow] = a4.w;
        *(float4*)&Bs[brow][bcol] = *(const float4*)(Wp + (size_t)k0 * HID);
        __syncthreads();

        #pragma unroll
        for (int k = 0; k < BK; k++) {
            float4 ra0 = *(const float4*)&As[k][tRow];
            float4 ra1 = *(const float4*)&As[k][tRow + 4];
            float4 rb0 = *(const float4*)&Bs[k][tCol];
            float4 rb1 = *(const float4*)&Bs[k][tCol + 4];
            float ra[TM] = {ra0.x, ra0.y, ra0.z, ra0.w, ra1.x, ra1.y, ra1.z, ra1.w};
            float rb[TN] = {rb0.x, rb0.y, rb0.z, rb0.w, rb1.x, rb1.y, rb1.z, rb1.w};
            #pragma unroll
            for (int i = 0; i < TM; i++)
                #pragma unroll
                for (int j = 0; j < TN; j++)
                    acc[i][j] = fmaf(ra[i], rb[j], acc[i][j]);
        }
        __syncthreads();
    }

    // Epilogue: add bias, scatter into [B,H,S,d]. The 8 contiguous cols of a
    // thread never cross a head boundary (tCol multiple of 8, HD=64).
    const int n  = n0 + tCol;
    const int h  = n >> 6;
    const int c0 = n & 63;
    float bi[TN];
    #pragma unroll
    for (int j = 0; j < TN; j++) bi[j] = bias[n + j];

    #pragma unroll
    for (int i = 0; i < TM; i++) {
        int m  = m0 + tRow + i;
        int bb = m >> 11;          // batch
        int s  = m & 2047;         // seq pos
        float* op = out + (((size_t)(bb * NH + h) * S2 + s) * HD + c0);
        float4 o0, o1;
        o0.x = acc[i][0] + bi[0]; o0.y = acc[i][1] + bi[1];
        o0.z = acc[i][2] + bi[2]; o0.w = acc[i][3] + bi[3];
        o1.x = acc[i][4] + bi[4]; o1.y = acc[i][5] + bi[5];
        o1.z = acc[i][6] + bi[6]; o1.w = acc[i][7] + bi[7];
        *(float4*)(op)     = o0;
        *(float4*)(op + 4) = o1;
    }
}

// ---------------------------------------------------------------------------
// Sparse attention: one warp per query row.
// Allowed keys for row i: local window [max(0,i-127), i] plus strided
// j = (i mod 128) + 128*t for t in [0, i/128). Masked entries contribute
// exactly 0 after softmax (exp underflow), so this is exact.
// Phase 1: lanes split head dim (float2/lane), serial over keys, shfl-reduce.
// Phase 2: warp softmax in smem; lanes split head dim for P@V.
// ---------------------------------------------------------------------------
__global__ __launch_bounds__(256)
void attn_kernel(const float* __restrict__ amask, float* __restrict__ out)
{
    __shared__ float pbuf[8][160];   // per-warp score buffer (n <= 144)

    const int warp = threadIdx.x >> 5;
    const int lane = threadIdx.x & 31;
    const int rid  = blockIdx.x * 8 + warp;   // global query-row id
    const int i    = rid & (S2 - 1);
    const int bh   = rid >> 11;               // 0..31
    const int b    = bh >> 4;

    const float* __restrict__ q  = g_q + (size_t)bh * S2 * HD;
    const float* __restrict__ v  = g_v + (size_t)bh * S2 * HD;
    const float* __restrict__ am = amask + b * S2;

    const float2 qi = *(const float2*)(q + (size_t)i * HD + (lane << 1));

    const int nstr  = i >> 7;
    const int jloc0 = (i > 127) ? (i - 127) : 0;
    const int nloc  = i - jloc0 + 1;
    const int n     = nstr + nloc;
    const int res   = i & 127;

    // Phase 1: scores
    for (int t = 0; t < n; t++) {
        int j = (t < nstr) ? (res + (t << 7)) : (jloc0 + (t - nstr));
        float2 kj = *(const float2*)(q + (size_t)j * HD + (lane << 1));
        float p = qi.x * kj.x + qi.y * kj.y;
        p += __shfl_xor_sync(0xffffffffu, p, 16);
        p += __shfl_xor_sync(0xffffffffu, p, 8);
        p += __shfl_xor_sync(0xffffffffu, p, 4);
        p += __shfl_xor_sync(0xffffffffu, p, 2);
        p += __shfl_xor_sync(0xffffffffu, p, 1);
        if (lane == 0) pbuf[warp][t] = p * 0.125f + am[j];
    }
    __syncwarp();

    // Softmax (unnormalized exp in pbuf, keep 1/sum for the end)
    float mx = -1e30f;
    for (int t = lane; t < n; t += 32) mx = fmaxf(mx, pbuf[warp][t]);
    mx = fmaxf(mx, __shfl_xor_sync(0xffffffffu, mx, 16));
    mx = fmaxf(mx, __shfl_xor_sync(0xffffffffu, mx, 8));
    mx = fmaxf(mx, __shfl_xor_sync(0xffffffffu, mx, 4));
    mx = fmaxf(mx, __shfl_xor_sync(0xffffffffu, mx, 2));
    mx = fmaxf(mx, __shfl_xor_sync(0xffffffffu, mx, 1));

    float sum = 0.0f;
    for (int t = lane; t < n; t += 32) {
        float e = __expf(pbuf[warp][t] - mx);
        pbuf[warp][t] = e;
        sum += e;
    }
    sum += __shfl_xor_sync(0xffffffffu, sum, 16);
    sum += __shfl_xor_sync(0xffffffffu, sum, 8);
    sum += __shfl_xor_sync(0xffffffffu, sum, 4);
    sum += __shfl_xor_sync(0xffffffffu, sum, 2);
    sum += __shfl_xor_sync(0xffffffffu, sum, 1);
    const float inv = 1.0f / sum;
    __syncwarp();

    // Phase 2: ctx = (sum_t e_t * v_j) * inv
    float accx = 0.0f, accy = 0.0f;
    for (int t = 0; t < n; t++) {
        int j = (t < nstr) ? (res + (t << 7)) : (jloc0 + (t - nstr));
        float p = pbuf[warp][t];
        float2 vv = *(const float2*)(v + (size_t)j * HD + (lane << 1));
        accx = fmaf(p, vv.x, accx);
        accy = fmaf(p, vv.y, accy);
    }
    float2 o;
    o.x = accx * inv;
    o.y = accy * inv;
    // out layout: [B, S, H*64]
    *(float2*)(out + ((size_t)(b * S2 + i) * (NH * HD)) + (bh & 15) * HD + (lane << 1)) = o;
}

// ---------------------------------------------------------------------------
// Launch
// Inputs (metadata order): hidden_states, attention_mask, W_q, b_q, W_v, b_v
// ---------------------------------------------------------------------------
extern "C" void kernel_launch(void* const* d_in, const int* in_sizes, int n_in,
                              void* d_out, int out_size)
{
    const float* hidden = (const float*)d_in[0];
    const float* amask  = (const float*)d_in[1];
    const float* Wq     = (const float*)d_in[2];
    const float* bq     = (const float*)d_in[3];
    const float* Wv     = (const float*)d_in[4];
    const float* bv     = (const float*)d_in[5];
    float* out = (float*)d_out;

    dim3 pgrid(HID / BN, (BATCH * S2) / BM, 2);   // (8, 32, 2)
    proj_kernel<<<pgrid, 256>>>(hidden, Wq, bq, Wv, bv);

    attn_kernel<<<NROWS / 8, 256>>>(amask, out);
}

// round 2
// speedup vs baseline: 1.3815x; 1.3815x over previous
#include <cuda_runtime.h>
#include <math_constants.h>

// Problem constants
#define S2    2048
#define HID   1024
#define NH    16
#define HD    64
#define BATCH 2
#define NROWS (BATCH * NH * S2)   // 65536 query rows total

// Scratch for projected Q and V in [B, H, S, d] layout (16 MB each).
__device__ float g_q[BATCH * NH * S2 * HD];
__device__ float g_v[BATCH * NH * S2 * HD];

// ---------------------------------------------------------------------------
// Projection GEMM (unchanged): C[m, n] = A[m, :] @ W[:, n] + bias[n]
// ---------------------------------------------------------------------------
#define BM 128
#define BN 128
#define BK 8
#define TM 8
#define TN 8

__global__ __launch_bounds__(256, 2)
void proj_kernel(const float* __restrict__ A,
                 const float* __restrict__ Wq, const float* __restrict__ bq,
                 const float* __restrict__ Wv, const float* __restrict__ bv)
{
    const float* __restrict__ W    = blockIdx.z ? Wv : Wq;
    const float* __restrict__ bias = blockIdx.z ? bv : bq;
    float* __restrict__ out        = blockIdx.z ? g_v : g_q;

    __shared__ float As[BK][BM];
    __shared__ float Bs[BK][BN];

    const int tid = threadIdx.x;
    const int m0  = blockIdx.y * BM;
    const int n0  = blockIdx.x * BN;

    const int arow = tid >> 1;
    const int acol = (tid & 1) << 2;
    const int brow = tid >> 5;
    const int bcol = (tid & 31) << 2;

    const int tRow = (tid >> 4) << 3;
    const int tCol = (tid & 15) << 3;

    const float* Ap = A + (m0 + arow) * HID + acol;
    const float* Wp = W + brow * HID + n0 + bcol;

    float acc[TM][TN];
    #pragma unroll
    for (int i = 0; i < TM; i++)
        #pragma unroll
        for (int j = 0; j < TN; j++) acc[i][j] = 0.0f;

    for (int k0 = 0; k0 < HID; k0 += BK) {
        float4 a4 = *(const float4*)(Ap + k0);
        As[acol + 0][arow] = a4.x;
        As[acol + 1][arow] = a4.y;
        As[acol + 2][arow] = a4.z;
        As[acol + 3][arow] = a4.w;
        *(float4*)&Bs[brow][bcol] = *(const float4*)(Wp + (size_t)k0 * HID);
        __syncthreads();

        #pragma unroll
        for (int k = 0; k < BK; k++) {
            float4 ra0 = *(const float4*)&As[k][tRow];
            float4 ra1 = *(const float4*)&As[k][tRow + 4];
            float4 rb0 = *(const float4*)&Bs[k][tCol];
            float4 rb1 = *(const float4*)&Bs[k][tCol + 4];
            float ra[TM] = {ra0.x, ra0.y, ra0.z, ra0.w, ra1.x, ra1.y, ra1.z, ra1.w};
            float rb[TN] = {rb0.x, rb0.y, rb0.z, rb0.w, rb1.x, rb1.y, rb1.z, rb1.w};
            #pragma unroll
            for (int i = 0; i < TM; i++)
                #pragma unroll
                for (int j = 0; j < TN; j++)
                    acc[i][j] = fmaf(ra[i], rb[j], acc[i][j]);
        }
        __syncthreads();
    }

    const int n  = n0 + tCol;
    const int h  = n >> 6;
    const int c0 = n & 63;
    float bi[TN];
    #pragma unroll
    for (int j = 0; j < TN; j++) bi[j] = bias[n + j];

    #pragma unroll
    for (int i = 0; i < TM; i++) {
        int m  = m0 + tRow + i;
        int bb = m >> 11;
        int s  = m & 2047;
        float* op = out + (((size_t)(bb * NH + h) * S2 + s) * HD + c0);
        float4 o0, o1;
        o0.x = acc[i][0] + bi[0]; o0.y = acc[i][1] + bi[1];
        o0.z = acc[i][2] + bi[2]; o0.w = acc[i][3] + bi[3];
        o1.x = acc[i][4] + bi[4]; o1.y = acc[i][5] + bi[5];
        o1.z = acc[i][6] + bi[6]; o1.w = acc[i][7] + bi[7];
        *(float4*)(op)     = o0;
        *(float4*)(op + 4) = o1;
    }
}

// ---------------------------------------------------------------------------
// Tiled sparse attention.
// Block: 32 query rows (i in [I0, I0+32)) of one (b,h). 256 threads.
// Key window: j in [I0-128, I0+32) -> 160 rows in smem. For row r (i=I0+r),
// allowed dense columns: c in [r, r+128] with j=jbase+c >= 0 (c=r is the
// t=1 stride key). Remaining strided keys j = i - 128t, t=2..i>>7, handled
// per-warp from L2. Masked entries are exactly 0 after softmax (fp32 exp
// underflow), so sparse evaluation is bit-exact vs the dense reference.
// ---------------------------------------------------------------------------
#define TQ    32
#define WIN   160
#define KPAD  165
#define QPAD  33
#define PPAD  33
#define CPAD  66

#define ATTN_SMEM_BYTES ((64*KPAD + 64*QPAD + WIN*PPAD + TQ*16 + TQ*CPAD) * 4)

__global__ __launch_bounds__(256, 2)
void attn_kernel(const float* __restrict__ amask, float* __restrict__ out)
{
    extern __shared__ float sm[];
    float* KV   = sm;                        // Ks_t[d][c] (score) / Vs[c][d] (ctx)
    float* Qs   = KV + 64 * KPAD;            // Qs_t[d][r]
    float* Ps   = Qs + 64 * QPAD;            // P_t[c][r]
    float* Sstr = Ps + WIN * PPAD;           // [TQ][16]
    float* Cstr = Sstr + TQ * 16;            // [TQ][CPAD]

    const int tid = threadIdx.x;
    const int tx  = tid & 31;
    const int ty  = tid >> 5;                // warp id 0..7
    const int I0  = blockIdx.x * TQ;
    const int bh  = blockIdx.y;
    const int b   = bh >> 4;
    const int jbase = I0 - 128;

    const float* __restrict__ q  = g_q + (size_t)bh * S2 * HD;
    const float* __restrict__ v  = g_v + (size_t)bh * S2 * HD;
    const float* __restrict__ am = amask + b * S2;

    // ---- stage Q tile (transposed) and K window (transposed) ----
    for (int idx = tid; idx < TQ * HD; idx += 256) {
        int r = idx >> 6, d = idx & 63;
        Qs[d * QPAD + r] = q[(size_t)(I0 + r) * HD + d];
    }
    for (int idx = tid; idx < WIN * HD; idx += 256) {
        int c = idx >> 6, d = idx & 63;
        int j = jbase + c;
        KV[d * KPAD + c] = (j >= 0) ? q[(size_t)j * HD + d] : 0.0f;
    }
    __syncthreads();

    // ---- dense score GEMM: 4 queries x 5 keys per thread ----
    float acc[4][5];
    #pragma unroll
    for (int qi = 0; qi < 4; qi++)
        #pragma unroll
        for (int u = 0; u < 5; u++) acc[qi][u] = 0.0f;

    #pragma unroll 8
    for (int d = 0; d < 64; d++) {
        float a0 = Qs[d * QPAD + ty * 4 + 0];
        float a1 = Qs[d * QPAD + ty * 4 + 1];
        float a2 = Qs[d * QPAD + ty * 4 + 2];
        float a3 = Qs[d * QPAD + ty * 4 + 3];
        #pragma unroll
        for (int u = 0; u < 5; u++) {
            float bb = KV[d * KPAD + tx + 32 * u];
            acc[0][u] = fmaf(a0, bb, acc[0][u]);
            acc[1][u] = fmaf(a1, bb, acc[1][u]);
            acc[2][u] = fmaf(a2, bb, acc[2][u]);
            acc[3][u] = fmaf(a3, bb, acc[3][u]);
        }
    }

    // mask + scale + attention_mask; write transposed P buffer
    #pragma unroll
    for (int u = 0; u < 5; u++) {
        int c = tx + 32 * u;
        int j = jbase + c;
        float amv = (j >= 0) ? am[j] : 0.0f;
        #pragma unroll
        for (int qi = 0; qi < 4; qi++) {
            int r = ty * 4 + qi;
            bool ok = (c >= r) && (c <= r + 128) && (j >= 0);
            Ps[c * PPAD + r] = ok ? (acc[qi][u] * 0.125f + amv) : -CUDART_INF_F;
        }
    }
    __syncthreads();

    // ---- reload KV buffer with V window (row-major) ----
    for (int idx = tid; idx < WIN * HD; idx += 256) {
        int c = idx >> 6, d = idx & 63;
        int j = jbase + c;
        KV[c * HD + d] = (j >= 0) ? v[(size_t)j * HD + d] : 0.0f;
    }

    // ---- per-warp: strided scores (t >= 2), softmax, strided ctx ----
    // warp ty owns rows 4ty .. 4ty+3
    #pragma unroll
    for (int qi = 0; qi < 4; qi++) {
        int r = ty * 4 + qi;
        int i = I0 + r;
        int nstr = i >> 7;
        float qa = Qs[tx * QPAD + r];
        float qb = Qs[(tx + 32) * QPAD + r];
        for (int t = 2; t <= nstr; t++) {
            int j = i - (t << 7);
            float ka = q[(size_t)j * HD + tx];
            float kb = q[(size_t)j * HD + tx + 32];
            float p = qa * ka + qb * kb;
            p += __shfl_xor_sync(0xffffffffu, p, 16);
            p += __shfl_xor_sync(0xffffffffu, p, 8);
            p += __shfl_xor_sync(0xffffffffu, p, 4);
            p += __shfl_xor_sync(0xffffffffu, p, 2);
            p += __shfl_xor_sync(0xffffffffu, p, 1);
            if (tx == 0) Sstr[r * 16 + t] = p * 0.125f + am[j];
        }
    }
    __syncwarp();

    #pragma unroll
    for (int qi = 0; qi < 4; qi++) {
        int r = ty * 4 + qi;
        int i = I0 + r;
        int nstr = i >> 7;

        float mx = -CUDART_INF_F;
        #pragma unroll
        for (int u = 0; u < 5; u++) mx = fmaxf(mx, Ps[(tx + 32 * u) * PPAD + r]);
        if (tx + 2 <= nstr) mx = fmaxf(mx, Sstr[r * 16 + tx + 2]);
        mx = fmaxf(mx, __shfl_xor_sync(0xffffffffu, mx, 16));
        mx = fmaxf(mx, __shfl_xor_sync(0xffffffffu, mx, 8));
        mx = fmaxf(mx, __shfl_xor_sync(0xffffffffu, mx, 4));
        mx = fmaxf(mx, __shfl_xor_sync(0xffffffffu, mx, 2));
        mx = fmaxf(mx, __shfl_xor_sync(0xffffffffu, mx, 1));

        float s = 0.0f;
        float e[5];
        #pragma unroll
        for (int u = 0; u < 5; u++) {
            e[u] = __expf(Ps[(tx + 32 * u) * PPAD + r] - mx);
            s += e[u];
        }
        float es = 0.0f;
        if (tx + 2 <= nstr) es = __expf(Sstr[r * 16 + tx + 2] - mx);
        s += es;
        s += __shfl_xor_sync(0xffffffffu, s, 16);
        s += __shfl_xor_sync(0xffffffffu, s, 8);
        s += __shfl_xor_sync(0xffffffffu, s, 4);
        s += __shfl_xor_sync(0xffffffffu, s, 2);
        s += __shfl_xor_sync(0xffffffffu, s, 1);
        float inv = 1.0f / s;

        #pragma unroll
        for (int u = 0; u < 5; u++) Ps[(tx + 32 * u) * PPAD + r] = e[u] * inv;

        // strided ctx: lanes over d; p broadcast from lane (t-2)
        float ax = 0.0f, ay = 0.0f;
        float pn = es * inv;
        for (int t = 2; t <= nstr; t++) {
            float p = __shfl_sync(0xffffffffu, pn, t - 2);
            int j = i - (t << 7);
            ax = fmaf(p, v[(size_t)j * HD + tx], ax);
            ay = fmaf(p, v[(size_t)j * HD + tx + 32], ay);
        }
        Cstr[r * CPAD + tx]      = ax;
        Cstr[r * CPAD + tx + 32] = ay;
    }
    __syncthreads();

    // ---- dense ctx GEMM: 4 queries x 2 d-cols per thread ----
    float o[4][2];
    #pragma unroll
    for (int qi = 0; qi < 4; qi++) { o[qi][0] = 0.0f; o[qi][1] = 0.0f; }

    #pragma unroll 4
    for (int c = 0; c < WIN; c++) {
        float b0 = KV[c * HD + 2 * tx];
        float b1 = KV[c * HD + 2 * tx + 1];
        #pragma unroll
        for (int qi = 0; qi < 4; qi++) {
            float a = Ps[c * PPAD + ty * 4 + qi];
            o[qi][0] = fmaf(a, b0, o[qi][0]);
            o[qi][1] = fmaf(a, b1, o[qi][1]);
        }
    }

    // ---- epilogue: add strided ctx, store [B, S, H*64] ----
    #pragma unroll
    for (int qi = 0; qi < 4; qi++) {
        int r = ty * 4 + qi;
        int i = I0 + r;
        float2 res;
        res.x = o[qi][0] + Cstr[r * CPAD + 2 * tx];
        res.y = o[qi][1] + Cstr[r * CPAD + 2 * tx + 1];
        *(float2*)(out + ((size_t)(b * S2 + i) * (NH * HD)) + (bh & 15) * HD + 2 * tx) = res;
    }
}

// ---------------------------------------------------------------------------
// Launch
// Inputs (metadata order): hidden_states, attention_mask, W_q, b_q, W_v, b_v
// ---------------------------------------------------------------------------
extern "C" void kernel_launch(void* const* d_in, const int* in_sizes, int n_in,
                              void* d_out, int out_size)
{
    const float* hidden = (const float*)d_in[0];
    const float* amask  = (const float*)d_in[1];
    const float* Wq     = (const float*)d_in[2];
    const float* bq     = (const float*)d_in[3];
    const float* Wv     = (const float*)d_in[4];
    const float* bv     = (const float*)d_in[5];
    float* out = (float*)d_out;

    cudaFuncSetAttribute(attn_kernel,
                         cudaFuncAttributeMaxDynamicSharedMemorySize,
                         ATTN_SMEM_BYTES);

    dim3 pgrid(HID / BN, (BATCH * S2) / BM, 2);   // (8, 32, 2)
    proj_kernel<<<pgrid, 256>>>(hidden, Wq, bq, Wv, bv);

    dim3 agrid(S2 / TQ, BATCH * NH);              // (64, 32)
    attn_kernel<<<agrid, 256, ATTN_SMEM_BYTES>>>(amask, out);
}

// round 3
// speedup vs baseline: 2.5756x; 1.8643x over previous
#include <cuda_runtime.h>
#include <math_constants.h>
#include <cstdint>

// Problem constants
#define S2    2048
#define HID   1024
#define NH    16
#define HD    64
#define BATCH 2
#define NROWS (BATCH * NH * S2)

// Scratch for projected Q and V in [B, H, S, d] layout (16 MB each).
__device__ float g_q[BATCH * NH * S2 * HD];
__device__ float g_v[BATCH * NH * S2 * HD];

// ---------------------------------------------------------------------------
// TF32 tensor-core projection GEMM: C[m,n] = A[m,:] @ W[:,n] + bias[n]
// A = hidden [4096 x 1024] row-major, W [1024 x 1024] row-major.
// Block tile 128x128, k-block 16, double-buffered smem.
// 8 warps, each 64(m) x 32(n) via mma.sync m16n8k8 (4 m-frags x 4 n-frags).
// Output scattered to [B,H,S,d]. blockIdx.z: 0 -> (W_q,g_q), 1 -> (W_v,g_v)
// ---------------------------------------------------------------------------
#define PBM 128
#define PBN 128
#define PBK 16
#define SSTR 136   // smem row stride (floats): bank = (8k + col) % 32

__device__ __forceinline__ uint32_t f2tf32(float x) {
    uint32_t r;
    asm("cvt.rna.tf32.f32 %0, %1;" : "=r"(r) : "f"(x));
    return r;
}

__device__ __forceinline__ void mma_tf32(float c[4], const uint32_t a[4],
                                         const uint32_t b[2]) {
    asm volatile(
        "mma.sync.aligned.m16n8k8.row.col.f32.tf32.tf32.f32 "
        "{%0,%1,%2,%3}, {%4,%5,%6,%7}, {%8,%9}, {%0,%1,%2,%3};"
        : "+f"(c[0]), "+f"(c[1]), "+f"(c[2]), "+f"(c[3])
        : "r"(a[0]), "r"(a[1]), "r"(a[2]), "r"(a[3]), "r"(b[0]), "r"(b[1]));
}

__global__ __launch_bounds__(256)
void proj_kernel(const float* __restrict__ A,
                 const float* __restrict__ Wq, const float* __restrict__ bq,
                 const float* __restrict__ Wv, const float* __restrict__ bv)
{
    const float* __restrict__ W    = blockIdx.z ? Wv : Wq;
    const float* __restrict__ bias = blockIdx.z ? bv : bq;
    float* __restrict__ out        = blockIdx.z ? g_v : g_q;

    __shared__ uint32_t As[2][PBK][SSTR];
    __shared__ uint32_t Bs[2][PBK][SSTR];

    const int tid  = threadIdx.x;
    const int lane = tid & 31;
    const int wid  = tid >> 5;
    const int gid  = lane >> 2;      // 0..7
    const int tig  = lane & 3;       // 0..3
    const int m0   = blockIdx.y * PBM;
    const int n0   = blockIdx.x * PBN;

    const int warp_m = wid >> 2;     // 0..1 -> 64 rows
    const int warp_n = wid & 3;      // 0..3 -> 32 cols
    const int mBase  = warp_m * 64;
    const int nBase  = warp_n * 32;

    // A loader: thread covers (m = tid>>2 + 64p, k quad kq = tid&3), p = 0,1
    const int am = tid >> 2;
    const int akq = tid & 3;
    // B loader: quad qi = tid + 256p: kr = qi>>5, nq = qi&31
    const float* Aptr = A + (size_t)(m0 + am) * HID + 4 * akq;
    const float* Wp0  = W + (size_t)(tid >> 5) * HID + n0 + 4 * (tid & 31);
    const float* Wp1  = W + (size_t)((tid + 256) >> 5) * HID + n0 + 4 * ((tid + 256) & 31);

    float c[4][4][4];
    #pragma unroll
    for (int f = 0; f < 4; f++)
        #pragma unroll
        for (int g = 0; g < 4; g++)
            #pragma unroll
            for (int i = 0; i < 4; i++) c[f][g][i] = 0.0f;

    float4 pa0, pa1, pb0, pb1;

    // prologue: load k-block 0
    pa0 = *(const float4*)(Aptr);
    pa1 = *(const float4*)(Aptr + (size_t)64 * HID);
    pb0 = *(const float4*)(Wp0);
    pb1 = *(const float4*)(Wp1);

    // store tile 0 into buffer 0
    {
        float va0[4] = {pa0.x, pa0.y, pa0.z, pa0.w};
        float va1[4] = {pa1.x, pa1.y, pa1.z, pa1.w};
        #pragma unroll
        for (int s = 0; s < 4; s++) {
            int j = (s + akq) & 3;            // rotation -> conflict-free
            As[0][4 * akq + j][am]      = f2tf32(va0[j]);
            As[0][4 * akq + j][am + 64] = f2tf32(va1[j]);
        }
        uint32_t* bp0 = &Bs[0][tid >> 5][4 * (tid & 31)];
        bp0[0] = f2tf32(pb0.x); bp0[1] = f2tf32(pb0.y);
        bp0[2] = f2tf32(pb0.z); bp0[3] = f2tf32(pb0.w);
        uint32_t* bp1 = &Bs[0][(tid + 256) >> 5][4 * ((tid + 256) & 31)];
        bp1[0] = f2tf32(pb1.x); bp1[1] = f2tf32(pb1.y);
        bp1[2] = f2tf32(pb1.z); bp1[3] = f2tf32(pb1.w);
    }
    __syncthreads();

    const int NKB = HID / PBK;   // 64
    for (int kb = 0; kb < NKB; kb++) {
        const int cur = kb & 1;
        const int nxt = cur ^ 1;

        if (kb + 1 < NKB) {
            const int kk = (kb + 1) * PBK;
            pa0 = *(const float4*)(Aptr + kk);
            pa1 = *(const float4*)(Aptr + (size_t)64 * HID + kk);
            pb0 = *(const float4*)(Wp0 + (size_t)kk * HID);
            pb1 = *(const float4*)(Wp1 + (size_t)kk * HID);
        }

        // compute current buffer: 2 k-steps of 8
        #pragma unroll
        for (int ks = 0; ks < PBK; ks += 8) {
            uint32_t a[4][4], b[4][2];
            #pragma unroll
            for (int f = 0; f < 4; f++) {
                int m = mBase + 16 * f;
                a[f][0] = As[cur][ks + tig][m + gid];
                a[f][1] = As[cur][ks + tig][m + gid + 8];
                a[f][2] = As[cur][ks + tig + 4][m + gid];
                a[f][3] = As[cur][ks + tig + 4][m + gid + 8];
            }
            #pragma unroll
            for (int g = 0; g < 4; g++) {
                int n = nBase + 8 * g;
                b[g][0] = Bs[cur][ks + tig][n + gid];
                b[g][1] = Bs[cur][ks + tig + 4][n + gid];
            }
            #pragma unroll
            for (int f = 0; f < 4; f++)
                #pragma unroll
                for (int g = 0; g < 4; g++)
                    mma_tf32(c[f][g], a[f], b[g]);
        }

        if (kb + 1 < NKB) {
            float va0[4] = {pa0.x, pa0.y, pa0.z, pa0.w};
            float va1[4] = {pa1.x, pa1.y, pa1.z, pa1.w};
            #pragma unroll
            for (int s = 0; s < 4; s++) {
                int j = (s + akq) & 3;
                As[nxt][4 * akq + j][am]      = f2tf32(va0[j]);
                As[nxt][4 * akq + j][am + 64] = f2tf32(va1[j]);
            }
            uint32_t* bp0 = &Bs[nxt][tid >> 5][4 * (tid & 31)];
            bp0[0] = f2tf32(pb0.x); bp0[1] = f2tf32(pb0.y);
            bp0[2] = f2tf32(pb0.z); bp0[3] = f2tf32(pb0.w);
            uint32_t* bp1 = &Bs[nxt][(tid + 256) >> 5][4 * ((tid + 256) & 31)];
            bp1[0] = f2tf32(pb1.x); bp1[1] = f2tf32(pb1.y);
            bp1[2] = f2tf32(pb1.z); bp1[3] = f2tf32(pb1.w);
        }
        __syncthreads();
    }

    // Epilogue: bias + scatter to [B,H,S,d].
    #pragma unroll
    for (int g = 0; g < 4; g++) {
        const int n  = n0 + nBase + 8 * g + 2 * tig;
        const int h  = n >> 6;
        const int cc = n & 63;
        const float b0 = bias[n];
        const float b1 = bias[n + 1];
        #pragma unroll
        for (int f = 0; f < 4; f++) {
            #pragma unroll
            for (int half = 0; half < 2; half++) {
                int m  = m0 + mBase + 16 * f + gid + 8 * half;
                int bb = m >> 11;
                int s  = m & 2047;
                float2 o;
                o.x = c[f][g][2 * half + 0] + b0;
                o.y = c[f][g][2 * half + 1] + b1;
                *(float2*)(out + (((size_t)(bb * NH + h) * S2 + s) * HD + cc)) = o;
            }
        }
    }
}

// ---------------------------------------------------------------------------
// Tiled sparse attention (unchanged from round 2; exact vs dense reference).
// ---------------------------------------------------------------------------
#define TQ    32
#define WIN   160
#define KPAD  165
#define QPAD  33
#define PPAD  33
#define CPAD  66

#define ATTN_SMEM_BYTES ((64*KPAD + 64*QPAD + WIN*PPAD + TQ*16 + TQ*CPAD) * 4)

__global__ __launch_bounds__(256, 2)
void attn_kernel(const float* __restrict__ amask, float* __restrict__ out)
{
    extern __shared__ float sm[];
    float* KV   = sm;
    float* Qs   = KV + 64 * KPAD;
    float* Ps   = Qs + 64 * QPAD;
    float* Sstr = Ps + WIN * PPAD;
    float* Cstr = Sstr + TQ * 16;

    const int tid = threadIdx.x;
    const int tx  = tid & 31;
    const int ty  = tid >> 5;
    const int I0  = blockIdx.x * TQ;
    const int bh  = blockIdx.y;
    const int b   = bh >> 4;
    const int jbase = I0 - 128;

    const float* __restrict__ q  = g_q + (size_t)bh * S2 * HD;
    const float* __restrict__ v  = g_v + (size_t)bh * S2 * HD;
    const float* __restrict__ am = amask + b * S2;

    for (int idx = tid; idx < TQ * HD; idx += 256) {
        int r = idx >> 6, d = idx & 63;
        Qs[d * QPAD + r] = q[(size_t)(I0 + r) * HD + d];
    }
    for (int idx = tid; idx < WIN * HD; idx += 256) {
        int c = idx >> 6, d = idx & 63;
        int j = jbase + c;
        KV[d * KPAD + c] = (j >= 0) ? q[(size_t)j * HD + d] : 0.0f;
    }
    __syncthreads();

    float acc[4][5];
    #pragma unroll
    for (int qi = 0; qi < 4; qi++)
        #pragma unroll
        for (int u = 0; u < 5; u++) acc[qi][u] = 0.0f;

    #pragma unroll 8
    for (int d = 0; d < 64; d++) {
        float a0 = Qs[d * QPAD + ty * 4 + 0];
        float a1 = Qs[d * QPAD + ty * 4 + 1];
        float a2 = Qs[d * QPAD + ty * 4 + 2];
        float a3 = Qs[d * QPAD + ty * 4 + 3];
        #pragma unroll
        for (int u = 0; u < 5; u++) {
            float bb = KV[d * KPAD + tx + 32 * u];
            acc[0][u] = fmaf(a0, bb, acc[0][u]);
            acc[1][u] = fmaf(a1, bb, acc[1][u]);
            acc[2][u] = fmaf(a2, bb, acc[2][u]);
            acc[3][u] = fmaf(a3, bb, acc[3][u]);
        }
    }

    #pragma unroll
    for (int u = 0; u < 5; u++) {
        int c = tx + 32 * u;
        int j = jbase + c;
        float amv = (j >= 0) ? am[j] : 0.0f;
        #pragma unroll
        for (int qi = 0; qi < 4; qi++) {
            int r = ty * 4 + qi;
            bool ok = (c >= r) && (c <= r + 128) && (j >= 0);
            Ps[c * PPAD + r] = ok ? (acc[qi][u] * 0.125f + amv) : -CUDART_INF_F;
        }
    }
    __syncthreads();

    for (int idx = tid; idx < WIN * HD; idx += 256) {
        int c = idx >> 6, d = idx & 63;
        int j = jbase + c;
        KV[c * HD + d] = (j >= 0) ? v[(size_t)j * HD + d] : 0.0f;
    }

    #pragma unroll
    for (int qi = 0; qi < 4; qi++) {
        int r = ty * 4 + qi;
        int i = I0 + r;
        int nstr = i >> 7;
        float qa = Qs[tx * QPAD + r];
        float qb = Qs[(tx + 32) * QPAD + r];
        for (int t = 2; t <= nstr; t++) {
            int j = i - (t << 7);
            float ka = q[(size_t)j * HD + tx];
            float kb = q[(size_t)j * HD + tx + 32];
            float p = qa * ka + qb * kb;
            p += __shfl_xor_sync(0xffffffffu, p, 16);
            p += __shfl_xor_sync(0xffffffffu, p, 8);
            p += __shfl_xor_sync(0xffffffffu, p, 4);
            p += __shfl_xor_sync(0xffffffffu, p, 2);
            p += __shfl_xor_sync(0xffffffffu, p, 1);
            if (tx == 0) Sstr[r * 16 + t] = p * 0.125f + am[j];
        }
    }
    __syncwarp();

    #pragma unroll
    for (int qi = 0; qi < 4; qi++) {
        int r = ty * 4 + qi;
        int i = I0 + r;
        int nstr = i >> 7;

        float mx = -CUDART_INF_F;
        #pragma unroll
        for (int u = 0; u < 5; u++) mx = fmaxf(mx, Ps[(tx + 32 * u) * PPAD + r]);
        if (tx + 2 <= nstr) mx = fmaxf(mx, Sstr[r * 16 + tx + 2]);
        mx = fmaxf(mx, __shfl_xor_sync(0xffffffffu, mx, 16));
        mx = fmaxf(mx, __shfl_xor_sync(0xffffffffu, mx, 8));
        mx = fmaxf(mx, __shfl_xor_sync(0xffffffffu, mx, 4));
        mx = fmaxf(mx, __shfl_xor_sync(0xffffffffu, mx, 2));
        mx = fmaxf(mx, __shfl_xor_sync(0xffffffffu, mx, 1));

        float s = 0.0f;
        float e[5];
        #pragma unroll
        for (int u = 0; u < 5; u++) {
            e[u] = __expf(Ps[(tx + 32 * u) * PPAD + r] - mx);
            s += e[u];
        }
        float es = 0.0f;
        if (tx + 2 <= nstr) es = __expf(Sstr[r * 16 + tx + 2] - mx);
        s += es;
        s += __shfl_xor_sync(0xffffffffu, s, 16);
        s += __shfl_xor_sync(0xffffffffu, s, 8);
        s += __shfl_xor_sync(0xffffffffu, s, 4);
        s += __shfl_xor_sync(0xffffffffu, s, 2);
        s += __shfl_xor_sync(0xffffffffu, s, 1);
        float inv = 1.0f / s;

        #pragma unroll
        for (int u = 0; u < 5; u++) Ps[(tx + 32 * u) * PPAD + r] = e[u] * inv;

        float ax = 0.0f, ay = 0.0f;
        float pn = es * inv;
        for (int t = 2; t <= nstr; t++) {
            float p = __shfl_sync(0xffffffffu, pn, t - 2);
            int j = i - (t << 7);
            ax = fmaf(p, v[(size_t)j * HD + tx], ax);
            ay = fmaf(p, v[(size_t)j * HD + tx + 32], ay);
        }
        Cstr[r * CPAD + tx]      = ax;
        Cstr[r * CPAD + tx + 32] = ay;
    }
    __syncthreads();

    float o[4][2];
    #pragma unroll
    for (int qi = 0; qi < 4; qi++) { o[qi][0] = 0.0f; o[qi][1] = 0.0f; }

    #pragma unroll 4
    for (int c = 0; c < WIN; c++) {
        float b0 = KV[c * HD + 2 * tx];
        float b1 = KV[c * HD + 2 * tx + 1];
        #pragma unroll
        for (int qi = 0; qi < 4; qi++) {
            float a = Ps[c * PPAD + ty * 4 + qi];
            o[qi][0] = fmaf(a, b0, o[qi][0]);
            o[qi][1] = fmaf(a, b1, o[qi][1]);
        }
    }

    #pragma unroll
    for (int qi = 0; qi < 4; qi++) {
        int r = ty * 4 + qi;
        int i = I0 + r;
        float2 res;
        res.x = o[qi][0] + Cstr[r * CPAD + 2 * tx];
        res.y = o[qi][1] + Cstr[r * CPAD + 2 * tx + 1];
        *(float2*)(out + ((size_t)(b * S2 + i) * (NH * HD)) + (bh & 15) * HD + 2 * tx) = res;
    }
}

// ---------------------------------------------------------------------------
// Launch
// ---------------------------------------------------------------------------
extern "C" void kernel_launch(void* const* d_in, const int* in_sizes, int n_in,
                              void* d_out, int out_size)
{
    const float* hidden = (const float*)d_in[0];
    const float* amask  = (const float*)d_in[1];
    const float* Wq     = (const float*)d_in[2];
    const float* bq     = (const float*)d_in[3];
    const float* Wv     = (const float*)d_in[4];
    const float* bv     = (const float*)d_in[5];
    float* out = (float*)d_out;

    cudaFuncSetAttribute(attn_kernel,
                         cudaFuncAttributeMaxDynamicSharedMemorySize,
                         ATTN_SMEM_BYTES);

    dim3 pgrid(HID / PBN, (BATCH * S2) / PBM, 2);   // (8, 32, 2)
    proj_kernel<<<pgrid, 256>>>(hidden, Wq, bq, Wv, bv);

    dim3 agrid(S2 / TQ, BATCH * NH);                // (64, 32)
    attn_kernel<<<agrid, 256, ATTN_SMEM_BYTES>>>(amask, out);
}

// round 5
// speedup vs baseline: 2.7803x; 1.0795x over previous
#include <cuda_runtime.h>
#include <math_constants.h>
#include <cstdint>

// Problem constants
#define S2    2048
#define HID   1024
#define NH    16
#define HD    64
#define BATCH 2
#define NROWS (BATCH * NH * S2)

// Scratch for projected Q and V in [B, H, S, d] layout (16 MB each).
__device__ float g_q[BATCH * NH * S2 * HD];
__device__ float g_v[BATCH * NH * S2 * HD];

// ---------------------------------------------------------------------------
// TF32 tensor-core projection GEMM: C[m,n] = A[m,:] @ W[:,n] + bias[n]
// Block tile 128x128, k-block 16, double-buffered smem.
// 8 warps, each 64(m) x 32(n) via mma.sync m16n8k8 (4 m-frags x 4 n-frags).
// ---------------------------------------------------------------------------
#define PBM 128
#define PBN 128
#define PBK 16
#define SSTR 136

__device__ __forceinline__ uint32_t f2tf32(float x) {
    uint32_t r;
    asm("cvt.rna.tf32.f32 %0, %1;" : "=r"(r) : "f"(x));
    return r;
}

__device__ __forceinline__ void mma_tf32(float c[4], const uint32_t a[4],
                                         const uint32_t b[2]) {
    asm volatile(
        "mma.sync.aligned.m16n8k8.row.col.f32.tf32.tf32.f32 "
        "{%0,%1,%2,%3}, {%4,%5,%6,%7}, {%8,%9}, {%0,%1,%2,%3};"
        : "+f"(c[0]), "+f"(c[1]), "+f"(c[2]), "+f"(c[3])
        : "r"(a[0]), "r"(a[1]), "r"(a[2]), "r"(a[3]), "r"(b[0]), "r"(b[1]));
}

__global__ __launch_bounds__(256)
void proj_kernel(const float* __restrict__ A,
                 const float* __restrict__ Wq, const float* __restrict__ bq,
                 const float* __restrict__ Wv, const float* __restrict__ bv)
{
    const float* __restrict__ W    = blockIdx.z ? Wv : Wq;
    const float* __restrict__ bias = blockIdx.z ? bv : bq;
    float* __restrict__ out        = blockIdx.z ? g_v : g_q;

    __shared__ uint32_t As[2][PBK][SSTR];
    __shared__ uint32_t Bs[2][PBK][SSTR];

    const int tid  = threadIdx.x;
    const int lane = tid & 31;
    const int wid  = tid >> 5;
    const int gid  = lane >> 2;
    const int tig  = lane & 3;
    const int m0   = blockIdx.y * PBM;
    const int n0   = blockIdx.x * PBN;

    const int warp_m = wid >> 2;
    const int warp_n = wid & 3;
    const int mBase  = warp_m * 64;
    const int nBase  = warp_n * 32;

    const int am = tid >> 2;
    const int akq = tid & 3;
    const float* Aptr = A + (size_t)(m0 + am) * HID + 4 * akq;
    const float* Wp0  = W + (size_t)(tid >> 5) * HID + n0 + 4 * (tid & 31);
    const float* Wp1  = W + (size_t)((tid + 256) >> 5) * HID + n0 + 4 * ((tid + 256) & 31);

    float c[4][4][4];
    #pragma unroll
    for (int f = 0; f < 4; f++)
        #pragma unroll
        for (int g = 0; g < 4; g++)
            #pragma unroll
            for (int i = 0; i < 4; i++) c[f][g][i] = 0.0f;

    float4 pa0, pa1, pb0, pb1;

    pa0 = *(const float4*)(Aptr);
    pa1 = *(const float4*)(Aptr + (size_t)64 * HID);
    pb0 = *(const float4*)(Wp0);
    pb1 = *(const float4*)(Wp1);

    {
        float va0[4] = {pa0.x, pa0.y, pa0.z, pa0.w};
        float va1[4] = {pa1.x, pa1.y, pa1.z, pa1.w};
        #pragma unroll
        for (int s = 0; s < 4; s++) {
            int j = (s + akq) & 3;
            As[0][4 * akq + j][am]      = f2tf32(va0[j]);
            As[0][4 * akq + j][am + 64] = f2tf32(va1[j]);
        }
        uint32_t* bp0 = &Bs[0][tid >> 5][4 * (tid & 31)];
        bp0[0] = f2tf32(pb0.x); bp0[1] = f2tf32(pb0.y);
        bp0[2] = f2tf32(pb0.z); bp0[3] = f2tf32(pb0.w);
        uint32_t* bp1 = &Bs[0][(tid + 256) >> 5][4 * ((tid + 256) & 31)];
        bp1[0] = f2tf32(pb1.x); bp1[1] = f2tf32(pb1.y);
        bp1[2] = f2tf32(pb1.z); bp1[3] = f2tf32(pb1.w);
    }
    __syncthreads();

    const int NKB = HID / PBK;
    for (int kb = 0; kb < NKB; kb++) {
        const int cur = kb & 1;
        const int nxt = cur ^ 1;

        if (kb + 1 < NKB) {
            const int kk = (kb + 1) * PBK;
            pa0 = *(const float4*)(Aptr + kk);
            pa1 = *(const float4*)(Aptr + (size_t)64 * HID + kk);
            pb0 = *(const float4*)(Wp0 + (size_t)kk * HID);
            pb1 = *(const float4*)(Wp1 + (size_t)kk * HID);
        }

        #pragma unroll
        for (int ks = 0; ks < PBK; ks += 8) {
            uint32_t a[4][4], b[4][2];
            #pragma unroll
            for (int f = 0; f < 4; f++) {
                int m = mBase + 16 * f;
                a[f][0] = As[cur][ks + tig][m + gid];
                a[f][1] = As[cur][ks + tig][m + gid + 8];
                a[f][2] = As[cur][ks + tig + 4][m + gid];
                a[f][3] = As[cur][ks + tig + 4][m + gid + 8];
            }
            #pragma unroll
            for (int g = 0; g < 4; g++) {
                int n = nBase + 8 * g;
                b[g][0] = Bs[cur][ks + tig][n + gid];
                b[g][1] = Bs[cur][ks + tig + 4][n + gid];
            }
            #pragma unroll
            for (int f = 0; f < 4; f++)
                #pragma unroll
                for (int g = 0; g < 4; g++)
                    mma_tf32(c[f][g], a[f], b[g]);
        }

        if (kb + 1 < NKB) {
            float va0[4] = {pa0.x, pa0.y, pa0.z, pa0.w};
            float va1[4] = {pa1.x, pa1.y, pa1.z, pa1.w};
            #pragma unroll
            for (int s = 0; s < 4; s++) {
                int j = (s + akq) & 3;
                As[nxt][4 * akq + j][am]      = f2tf32(va0[j]);
                As[nxt][4 * akq + j][am + 64] = f2tf32(va1[j]);
            }
            uint32_t* bp0 = &Bs[nxt][tid >> 5][4 * (tid & 31)];
            bp0[0] = f2tf32(pb0.x); bp0[1] = f2tf32(pb0.y);
            bp0[2] = f2tf32(pb0.z); bp0[3] = f2tf32(pb0.w);
            uint32_t* bp1 = &Bs[nxt][(tid + 256) >> 5][4 * ((tid + 256) & 31)];
            bp1[0] = f2tf32(pb1.x); bp1[1] = f2tf32(pb1.y);
            bp1[2] = f2tf32(pb1.z); bp1[3] = f2tf32(pb1.w);
        }
        __syncthreads();
    }

    #pragma unroll
    for (int g = 0; g < 4; g++) {
        const int n  = n0 + nBase + 8 * g + 2 * tig;
        const int h  = n >> 6;
        const int cc = n & 63;
        const float b0 = bias[n];
        const float b1 = bias[n + 1];
        #pragma unroll
        for (int f = 0; f < 4; f++) {
            #pragma unroll
            for (int half = 0; half < 2; half++) {
                int m  = m0 + mBase + 16 * f + gid + 8 * half;
                int bb = m >> 11;
                int s  = m & 2047;
                float2 o;
                o.x = c[f][g][2 * half + 0] + b0;
                o.y = c[f][g][2 * half + 1] + b1;
                *(float2*)(out + (((size_t)(bb * NH + h) * S2 + s) * HD + cc)) = o;
            }
        }
    }
}

// ---------------------------------------------------------------------------
// Tiled sparse attention, smem-slimmed for 3 blocks/SM.
// KV: 64x161 (K transposed, score phase) / 160x64 (V row-major, ctx phase)
// QC: Qs 64x33 (score + strided phases), then ALIASED as Cstr 32x66 after a
//     full __syncthreads separates last Qs read from first Cstr write.
// Ps: 160x33, Sstr: 32x16.  Total 18208 floats = 72832 B -> 3 CTAs/SM.
// ---------------------------------------------------------------------------
#define TQ    32
#define WIN   160
#define KPAD  161
#define QPAD  33
#define PPAD  33
#define CPAD  66

#define ATTN_SMEM_FLOATS (64*KPAD + 64*QPAD + WIN*PPAD + TQ*16)
#define ATTN_SMEM_BYTES  (ATTN_SMEM_FLOATS * 4)

__global__ __launch_bounds__(256, 3)
void attn_kernel(const float* __restrict__ amask, float* __restrict__ out)
{
    extern __shared__ float sm[];
    float* KV   = sm;                        // 64*161
    float* QC   = KV + 64 * KPAD;            // Qs then Cstr (2112 floats)
    float* Ps   = QC + 64 * QPAD;            // 160*33
    float* Sstr = Ps + WIN * PPAD;           // 32*16
    float* Qs   = QC;
    float* Cstr = QC;

    const int tid = threadIdx.x;
    const int tx  = tid & 31;
    const int ty  = tid >> 5;
    const int I0  = blockIdx.x * TQ;
    const int bh  = blockIdx.y;
    const int b   = bh >> 4;
    const int jbase = I0 - 128;

    const float* __restrict__ q  = g_q + (size_t)bh * S2 * HD;
    const float* __restrict__ v  = g_v + (size_t)bh * S2 * HD;
    const float* __restrict__ am = amask + b * S2;

    // ---- stage Q tile (transposed) and K window (transposed) ----
    for (int idx = tid; idx < TQ * HD; idx += 256) {
        int r = idx >> 6, d = idx & 63;
        Qs[d * QPAD + r] = q[(size_t)(I0 + r) * HD + d];
    }
    for (int idx = tid; idx < WIN * HD; idx += 256) {
        int c = idx >> 6, d = idx & 63;
        int j = jbase + c;
        KV[d * KPAD + c] = (j >= 0) ? q[(size_t)j * HD + d] : 0.0f;
    }
    __syncthreads();

    // ---- dense score GEMM: 4 queries x 5 keys per thread ----
    float acc[4][5];
    #pragma unroll
    for (int qi = 0; qi < 4; qi++)
        #pragma unroll
        for (int u = 0; u < 5; u++) acc[qi][u] = 0.0f;

    #pragma unroll 8
    for (int d = 0; d < 64; d++) {
        float a0 = Qs[d * QPAD + ty * 4 + 0];
        float a1 = Qs[d * QPAD + ty * 4 + 1];
        float a2 = Qs[d * QPAD + ty * 4 + 2];
        float a3 = Qs[d * QPAD + ty * 4 + 3];
        #pragma unroll
        for (int u = 0; u < 5; u++) {
            float bb = KV[d * KPAD + tx + 32 * u];
            acc[0][u] = fmaf(a0, bb, acc[0][u]);
            acc[1][u] = fmaf(a1, bb, acc[1][u]);
            acc[2][u] = fmaf(a2, bb, acc[2][u]);
            acc[3][u] = fmaf(a3, bb, acc[3][u]);
        }
    }

    // mask + scale + attention_mask; transposed P buffer
    #pragma unroll
    for (int u = 0; u < 5; u++) {
        int c = tx + 32 * u;
        int j = jbase + c;
        float amv = (j >= 0) ? am[j] : 0.0f;
        #pragma unroll
        for (int qi = 0; qi < 4; qi++) {
            int r = ty * 4 + qi;
            bool ok = (c >= r) && (c <= r + 128) && (j >= 0);
            Ps[c * PPAD + r] = ok ? (acc[qi][u] * 0.125f + amv) : -CUDART_INF_F;
        }
    }
    __syncthreads();   // KV-K reads done -> safe to overwrite with V

    // ---- reload KV buffer with V window (row-major) ----
    for (int idx = tid; idx < WIN * HD; idx += 256) {
        int c = idx >> 6, d = idx & 63;
        int j = jbase + c;
        KV[c * HD + d] = (j >= 0) ? v[(size_t)j * HD + d] : 0.0f;
    }

    // ---- strided scores (t >= 2): last use of Qs ----
    #pragma unroll
    for (int qi = 0; qi < 4; qi++) {
        int r = ty * 4 + qi;
        int i = I0 + r;
        int nstr = i >> 7;
        float qa = Qs[tx * QPAD + r];
        float qb = Qs[(tx + 32) * QPAD + r];
        for (int t = 2; t <= nstr; t++) {
            int j = i - (t << 7);
            float ka = q[(size_t)j * HD + tx];
            float kb = q[(size_t)j * HD + tx + 32];
            float p = qa * ka + qb * kb;
            p += __shfl_xor_sync(0xffffffffu, p, 16);
            p += __shfl_xor_sync(0xffffffffu, p, 8);
            p += __shfl_xor_sync(0xffffffffu, p, 4);
            p += __shfl_xor_sync(0xffffffffu, p, 2);
            p += __shfl_xor_sync(0xffffffffu, p, 1);
            if (tx == 0) Sstr[r * 16 + t] = p * 0.125f + am[j];
        }
    }
    __syncthreads();   // Qs dead everywhere -> Cstr may alias it

    // ---- softmax + strided ctx (writes Cstr over old Qs) ----
    #pragma unroll
    for (int qi = 0; qi < 4; qi++) {
        int r = ty * 4 + qi;
        int i = I0 + r;
        int nstr = i >> 7;

        float mx = -CUDART_INF_F;
        #pragma unroll
        for (int u = 0; u < 5; u++) mx = fmaxf(mx, Ps[(tx + 32 * u) * PPAD + r]);
        if (tx + 2 <= nstr) mx = fmaxf(mx, Sstr[r * 16 + tx + 2]);
        mx = fmaxf(mx, __shfl_xor_sync(0xffffffffu, mx, 16));
        mx = fmaxf(mx, __shfl_xor_sync(0xffffffffu, mx, 8));
        mx = fmaxf(mx, __shfl_xor_sync(0xffffffffu, mx, 4));
        mx = fmaxf(mx, __shfl_xor_sync(0xffffffffu, mx, 2));
        mx = fmaxf(mx, __shfl_xor_sync(0xffffffffu, mx, 1));

        float s = 0.0f;
        float e[5];
        #pragma unroll
        for (int u = 0; u < 5; u++) {
            e[u] = __expf(Ps[(tx + 32 * u) * PPAD + r] - mx);
            s += e[u];
        }
        float es = 0.0f;
        if (tx + 2 <= nstr) es = __expf(Sstr[r * 16 + tx + 2] - mx);
        s += es;
        s += __shfl_xor_sync(0xffffffffu, s, 16);
        s += __shfl_xor_sync(0xffffffffu, s, 8);
        s += __shfl_xor_sync(0xffffffffu, s, 4);
        s += __shfl_xor_sync(0xffffffffu, s, 2);
        s += __shfl_xor_sync(0xffffffffu, s, 1);
        float inv = 1.0f / s;

        #pragma unroll
        for (int u = 0; u < 5; u++) Ps[(tx + 32 * u) * PPAD + r] = e[u] * inv;

        float ax = 0.0f, ay = 0.0f;
        float pn = es * inv;
        for (int t = 2; t <= nstr; t++) {
            float p = __shfl_sync(0xffffffffu, pn, t - 2);
            int j = i - (t << 7);
            ax = fmaf(p, v[(size_t)j * HD + tx], ax);
            ay = fmaf(p, v[(size_t)j * HD + tx + 32], ay);
        }
        Cstr[r * CPAD + tx]      = ax;
        Cstr[r * CPAD + tx + 32] = ay;
    }
    __syncthreads();   // V staged + Cstr written before dense ctx

    // ---- dense ctx GEMM: 4 queries x 2 d-cols per thread (float2 loads) ----
    float o[4][2];
    #pragma unroll
    for (int qi = 0; qi < 4; qi++) { o[qi][0] = 0.0f; o[qi][1] = 0.0f; }

    #pragma unroll 4
    for (int c = 0; c < WIN; c++) {
        float2 bv2 = ((const float2*)(KV + c * HD))[tx];
        #pragma unroll
        for (int qi = 0; qi < 4; qi++) {
            float a = Ps[c * PPAD + ty * 4 + qi];
            o[qi][0] = fmaf(a, bv2.x, o[qi][0]);
            o[qi][1] = fmaf(a, bv2.y, o[qi][1]);
        }
    }

    // ---- epilogue: add strided ctx, store [B, S, H*64] ----
    #pragma unroll
    for (int qi = 0; qi < 4; qi++) {
        int r = ty * 4 + qi;
        int i = I0 + r;
        float2 cs = ((const float2*)(Cstr + r * CPAD))[tx];
        float2 res;
        res.x = o[qi][0] + cs.x;
        res.y = o[qi][1] + cs.y;
        *(float2*)(out + ((size_t)(b * S2 + i) * (NH * HD)) + (bh & 15) * HD + 2 * tx) = res;
    }
}

// ---------------------------------------------------------------------------
// Launch
// ---------------------------------------------------------------------------
extern "C" void kernel_launch(void* const* d_in, const int* in_sizes, int n_in,
                              void* d_out, int out_size)
{
    const float* hidden = (const float*)d_in[0];
    const float* amask  = (const float*)d_in[1];
    const float* Wq     = (const float*)d_in[2];
    const float* bq     = (const float*)d_in[3];
    const float* Wv     = (const float*)d_in[4];
    const float* bv     = (const float*)d_in[5];
    float* out = (float*)d_out;

    cudaFuncSetAttribute(attn_kernel,
                         cudaFuncAttributeMaxDynamicSharedMemorySize,
                         ATTN_SMEM_BYTES);

    dim3 pgrid(HID / PBN, (BATCH * S2) / PBM, 2);   // (8, 32, 2)
    proj_kernel<<<pgrid, 256>>>(hidden, Wq, bq, Wv, bv);

    dim3 agrid(S2 / TQ, BATCH * NH);                // (64, 32)
    attn_kernel<<<agrid, 256, ATTN_SMEM_BYTES>>>(amask, out);
}